// round 15
// baseline (speedup 1.0000x reference)
#include <cuda_runtime.h>

// Fused SSIM, separable 11x11 gaussian, f32x2-packed FMA.
// R15 = R14 (best: 96.7us, fma 67.9%/alu 10.7%, clock-merit 65.7) with ONE
// change: __launch_bounds__(256,3) -> (256,4). regs=62 already fits the
// 64-reg cap; smem 48840*4=195KB <= 227KB. 4th resident CTA (+33% warps)
// fills barrier-drain / task-imbalance / LDS-latency holes in the fma pipe.

#define TW   64
#define TH   32
#define KSZ  11
#define IN_W (TW + 10)        // 74
#define VBP2 (TH + 1)         // 33 (odd stride in 8B units -> conflict-free)
#define RV   4
#define NRG  (TH / RV)        // 8
#define NTASK (IN_W * NRG)    // 592
#define RH   8
#define NTHR 256

#define IMG_W 1024
#define IMG_H 1024

typedef unsigned long long u64;

__device__ constexpr float GW[KSZ] = {
    0.00102838f, 0.00759896f, 0.03600077f, 0.10936074f, 0.21300516f,
    0.26601160f, 0.21300516f, 0.10936074f, 0.03600077f, 0.00759896f,
    0.00102838f
};

__device__ double g_acc = 0.0;
__device__ unsigned int g_done = 0;

__device__ __forceinline__ u64 pack2(float lo, float hi) {
    u64 d; asm("mov.b64 %0, {%1,%2};" : "=l"(d) : "f"(lo), "f"(hi)); return d;
}
__device__ __forceinline__ void unpack2(u64 v, float& lo, float& hi) {
    asm("mov.b64 {%0,%1}, %2;" : "=f"(lo), "=f"(hi) : "l"(v));
}
__device__ __forceinline__ u64 fma2(u64 a, u64 b, u64 c) {
    u64 d; asm("fma.rn.f32x2 %0, %1, %2, %3;" : "=l"(d) : "l"(a), "l"(b), "l"(c)); return d;
}
__device__ __forceinline__ u64 mul2(u64 a, u64 b) {
    u64 d; asm("mul.rn.f32x2 %0, %1, %2;" : "=l"(d) : "l"(a), "l"(b)); return d;
}
// Symmetric packed-weight lookup (6 unique regs; k compile-time const).
__device__ __forceinline__ u64 wsym(const u64* wp, int k) {
    return wp[(k < 6) ? k : (10 - k)];
}

extern __shared__ unsigned char smem_raw[];

template <bool GUARD>
__device__ __forceinline__ void vtask(const float* __restrict__ img1,
                                      const float* __restrict__ img2,
                                      long base,
                                      int bx0, int by0,
                                      int c, int r0,
                                      const u64* __restrict__ wp,
                                      u64* __restrict__ vb01,
                                      u64* __restrict__ vb23,
                                      float* __restrict__ vb4) {
    int gx = bx0 + c;
    bool x_ok = true;
    if (GUARD) x_ok = (gx >= 0) & (gx < IMG_W);

    // IMG_W compile-time: row offsets are immediates folded into LDG.
    const float* p1 = img1 + base + ((long)(by0 + r0) << 10) + gx;
    const float* p2 = img2 + base + ((long)(by0 + r0) << 10) + gx;

    u64 a01[RV], a23[RV];
    float a4[RV];
    #pragma unroll
    for (int j = 0; j < RV; ++j) { a01[j] = 0ull; a23[j] = 0ull; a4[j] = 0.f; }

    #pragma unroll
    for (int r = 0; r < RV + KSZ - 1; ++r) {          // 14 rows
        float vx, vy;
        if (GUARD) {
            int gy = by0 + r0 + r;
            bool ok = x_ok & (gy >= 0) & (gy < IMG_H);
            vx = ok ? p1[r << 10] : 0.f;
            vy = ok ? p2[r << 10] : 0.f;
        } else {
            vx = p1[r << 10];
            vy = p2[r << 10];
        }
        u64 vxy   = pack2(vx, vy);
        u64 pxxyy = mul2(vxy, vxy);
        float pxy = vx * vy;
        #pragma unroll
        for (int j = 0; j < RV; ++j) {
            int k = r - j;
            if (k >= 0 && k < KSZ) {
                a01[j] = fma2(wsym(wp, k), vxy,   a01[j]);
                a23[j] = fma2(wsym(wp, k), pxxyy, a23[j]);
                a4[j] += GW[k] * pxy;                 // FFMA-imm, no regs
            }
        }
    }
    #pragma unroll
    for (int j = 0; j < RV; ++j) {
        int o = c * VBP2 + r0 + j;
        vb01[o] = a01[j];
        vb23[o] = a23[j];
        vb4[o]  = a4[j];
    }
}

__global__ __launch_bounds__(NTHR, 4)
void ssim_main(const float* __restrict__ img1,
               const float* __restrict__ img2,
               float* __restrict__ out,
               unsigned int nblocks, double inv_n) {
    u64*   vb01 = (u64*)smem_raw;                    // [IN_W][VBP2] u64
    u64*   vb23 = vb01 + IN_W * VBP2;
    float* vb4  = (float*)(vb23 + IN_W * VBP2);
    __shared__ float warpsum[NTHR / 32];

    const int tid = threadIdx.x;
    const int bx0 = blockIdx.x * TW - 5;
    const int by0 = blockIdx.y * TH - 5;
    const long base = (long)blockIdx.z << 20;        // z * 1024 * 1024

    // 6 unique packed weights (symmetry) -> 12 registers.
    u64 wp[6];
    #pragma unroll
    for (int k = 0; k < 6; ++k) wp[k] = pack2(GW[k], GW[k]);

    const bool interior = (bx0 >= 0) & (by0 >= 0) &
                          (bx0 + IN_W <= IMG_W) & (by0 + TH + 10 <= IMG_H);

    // ---- Vertical pass: GMEM -> registers (sliding window) -> vb ----
    if (interior) {
        #pragma unroll 1
        for (int task = tid; task < NTASK; task += NTHR) {
            int rg = task / IN_W;
            int c  = task - rg * IN_W;
            vtask<false>(img1, img2, base, bx0, by0, c, rg * RV,
                         wp, vb01, vb23, vb4);
        }
    } else {
        #pragma unroll 1
        for (int task = tid; task < NTASK; task += NTHR) {
            int rg = task / IN_W;
            int c  = task - rg * IN_W;
            vtask<true>(img1, img2, base, bx0, by0, c, rg * RV,
                        wp, vb01, vb23, vb4);
        }
    }
    __syncthreads();

    // ---- Horizontal pass + SSIM ----
    const int r  = tid & (TH - 1);       // lanes -> consecutive rows
    const int x0 = (tid >> 5) * RH;      // 8 x-groups of RH outputs

    u64 b01[RH], b23[RH];
    float b4[RH];
    #pragma unroll
    for (int j = 0; j < RH; ++j) { b01[j] = 0ull; b23[j] = 0ull; b4[j] = 0.f; }

    #pragma unroll
    for (int i = 0; i < RH + KSZ - 1; ++i) {          // 18 x positions
        int o = (x0 + i) * VBP2 + r;
        u64 v01 = vb01[o];
        u64 v23 = vb23[o];
        float v4 = vb4[o];
        #pragma unroll
        for (int j = 0; j < RH; ++j) {
            int k = i - j;
            if (k >= 0 && k < KSZ) {
                b01[j] = fma2(wsym(wp, k), v01, b01[j]);
                b23[j] = fma2(wsym(wp, k), v23, b23[j]);
                b4[j] += GW[k] * v4;                  // FFMA-imm
            }
        }
    }

    const float C1 = 1e-4f, C2 = 9e-4f;
    float ssum = 0.f;
    #pragma unroll
    for (int j = 0; j < RH; ++j) {
        float mx, my, mxx, myy;
        unpack2(b01[j], mx, my);
        unpack2(b23[j], mxx, myy);
        float mxy = b4[j];
        float mx2 = mx * mx, my2 = my * my, mxmy = mx * my;
        float sxx = mxx - mx2;
        float syy = myy - my2;
        float sxy = mxy - mxmy;
        float num = (2.f * mxmy + C1) * (2.f * sxy + C2);
        float den = (mx2 + my2 + C1) * (sxx + syy + C2);
        ssum += __fdividef(num, den);
    }

    // ---- Block reduce -> one double atomic per block ----
    #pragma unroll
    for (int o = 16; o > 0; o >>= 1)
        ssum += __shfl_down_sync(0xffffffffu, ssum, o);
    int lane = tid & 31, wid = tid >> 5;
    if (lane == 0) warpsum[wid] = ssum;
    __syncthreads();
    if (wid == 0 && lane == 0) {
        float v = 0.f;
        #pragma unroll
        for (int w = 0; w < NTHR / 32; ++w) v += warpsum[w];
        atomicAdd(&g_acc, (double)v);

        // Last-block-done finalize: write mean, reset accumulator for the
        // next graph replay. atomicInc wraps the counter back to 0.
        __threadfence();
        unsigned int prev = atomicInc(&g_done, nblocks - 1);
        if (prev == nblocks - 1) {
            __threadfence();
            out[0] = (float)(g_acc * inv_n);
            g_acc = 0.0;
        }
    }
}

extern "C" void kernel_launch(void* const* d_in, const int* in_sizes, int n_in,
                              void* d_out, int out_size) {
    const float* img1 = (const float*)d_in[0];
    const float* img2 = (const float*)d_in[1];
    float* out = (float*)d_out;

    const int B = in_sizes[0] / (IMG_W * IMG_H);

    const int smem_bytes = IN_W * VBP2 * (8 + 8 + 4);   // 48840 B
    cudaFuncSetAttribute(ssim_main, cudaFuncAttributeMaxDynamicSharedMemorySize,
                         smem_bytes);

    dim3 blk(NTHR);
    dim3 grd(IMG_W / TW, IMG_H / TH, B);
    unsigned int nblocks = grd.x * grd.y * grd.z;
    double inv_n = 1.0 / ((double)B * IMG_W * IMG_H);

    ssim_main<<<grd, blk, smem_bytes>>>(img1, img2, out, nblocks, inv_n);
}

// round 16
// speedup vs baseline: 1.0307x; 1.0307x over previous
#include <cuda_runtime.h>

// Fused SSIM, separable 11x11 gaussian, f32x2-packed FMA.
// R16 = R15 with ONE change: vb01/vb23 interleaved into a ulonglong2 array,
// so the vertical pass stores STS.128 (was 2x STS.64) and the horizontal
// pass loads LDS.128 (was 2x LDS.64). Bank-verified conflict-free in both
// passes (8-lane phases cover banks exactly). ~3.5% fewer issue slots,
// half the vb LSU wavefronts. Everything else byte-identical.

#define TW   64
#define TH   32
#define KSZ  11
#define IN_W (TW + 10)        // 74
#define VBP2 (TH + 1)         // 33 (odd stride -> conflict-free phases)
#define RV   4
#define NRG  (TH / RV)        // 8
#define NTASK (IN_W * NRG)    // 592
#define RH   8
#define NTHR 256

#define IMG_W 1024
#define IMG_H 1024

typedef unsigned long long u64;

__device__ constexpr float GW[KSZ] = {
    0.00102838f, 0.00759896f, 0.03600077f, 0.10936074f, 0.21300516f,
    0.26601160f, 0.21300516f, 0.10936074f, 0.03600077f, 0.00759896f,
    0.00102838f
};

__device__ double g_acc = 0.0;
__device__ unsigned int g_done = 0;

__device__ __forceinline__ u64 pack2(float lo, float hi) {
    u64 d; asm("mov.b64 %0, {%1,%2};" : "=l"(d) : "f"(lo), "f"(hi)); return d;
}
__device__ __forceinline__ void unpack2(u64 v, float& lo, float& hi) {
    asm("mov.b64 {%0,%1}, %2;" : "=f"(lo), "=f"(hi) : "l"(v));
}
__device__ __forceinline__ u64 fma2(u64 a, u64 b, u64 c) {
    u64 d; asm("fma.rn.f32x2 %0, %1, %2, %3;" : "=l"(d) : "l"(a), "l"(b), "l"(c)); return d;
}
__device__ __forceinline__ u64 mul2(u64 a, u64 b) {
    u64 d; asm("mul.rn.f32x2 %0, %1, %2;" : "=l"(d) : "l"(a), "l"(b)); return d;
}
// Symmetric packed-weight lookup (6 unique regs; k compile-time const).
__device__ __forceinline__ u64 wsym(const u64* wp, int k) {
    return wp[(k < 6) ? k : (10 - k)];
}

extern __shared__ unsigned char smem_raw[];

template <bool GUARD>
__device__ __forceinline__ void vtask(const float* __restrict__ img1,
                                      const float* __restrict__ img2,
                                      long base,
                                      int bx0, int by0,
                                      int c, int r0,
                                      const u64* __restrict__ wp,
                                      ulonglong2* __restrict__ vbA,
                                      float* __restrict__ vb4) {
    int gx = bx0 + c;
    bool x_ok = true;
    if (GUARD) x_ok = (gx >= 0) & (gx < IMG_W);

    // IMG_W compile-time: row offsets are immediates folded into LDG.
    const float* p1 = img1 + base + ((long)(by0 + r0) << 10) + gx;
    const float* p2 = img2 + base + ((long)(by0 + r0) << 10) + gx;

    u64 a01[RV], a23[RV];
    float a4[RV];
    #pragma unroll
    for (int j = 0; j < RV; ++j) { a01[j] = 0ull; a23[j] = 0ull; a4[j] = 0.f; }

    #pragma unroll
    for (int r = 0; r < RV + KSZ - 1; ++r) {          // 14 rows
        float vx, vy;
        if (GUARD) {
            int gy = by0 + r0 + r;
            bool ok = x_ok & (gy >= 0) & (gy < IMG_H);
            vx = ok ? p1[r << 10] : 0.f;
            vy = ok ? p2[r << 10] : 0.f;
        } else {
            vx = p1[r << 10];
            vy = p2[r << 10];
        }
        u64 vxy   = pack2(vx, vy);
        u64 pxxyy = mul2(vxy, vxy);
        float pxy = vx * vy;
        #pragma unroll
        for (int j = 0; j < RV; ++j) {
            int k = r - j;
            if (k >= 0 && k < KSZ) {
                a01[j] = fma2(wsym(wp, k), vxy,   a01[j]);
                a23[j] = fma2(wsym(wp, k), pxxyy, a23[j]);
                a4[j] += GW[k] * pxy;                 // FFMA-imm, no regs
            }
        }
    }
    #pragma unroll
    for (int j = 0; j < RV; ++j) {
        int o = c * VBP2 + r0 + j;
        vbA[o] = make_ulonglong2(a01[j], a23[j]);    // STS.128
        vb4[o] = a4[j];
    }
}

__global__ __launch_bounds__(NTHR, 4)
void ssim_main(const float* __restrict__ img1,
               const float* __restrict__ img2,
               float* __restrict__ out,
               unsigned int nblocks, double inv_n) {
    ulonglong2* vbA = (ulonglong2*)smem_raw;         // [IN_W*VBP2] 16B each
    float*      vb4 = (float*)(vbA + IN_W * VBP2);   // [IN_W*VBP2] 4B each
    __shared__ float warpsum[NTHR / 32];

    const int tid = threadIdx.x;
    const int bx0 = blockIdx.x * TW - 5;
    const int by0 = blockIdx.y * TH - 5;
    const long base = (long)blockIdx.z << 20;        // z * 1024 * 1024

    // 6 unique packed weights (symmetry) -> 12 registers.
    u64 wp[6];
    #pragma unroll
    for (int k = 0; k < 6; ++k) wp[k] = pack2(GW[k], GW[k]);

    const bool interior = (bx0 >= 0) & (by0 >= 0) &
                          (bx0 + IN_W <= IMG_W) & (by0 + TH + 10 <= IMG_H);

    // ---- Vertical pass: GMEM -> registers (sliding window) -> vb ----
    if (interior) {
        #pragma unroll 1
        for (int task = tid; task < NTASK; task += NTHR) {
            int rg = task / IN_W;
            int c  = task - rg * IN_W;
            vtask<false>(img1, img2, base, bx0, by0, c, rg * RV,
                         wp, vbA, vb4);
        }
    } else {
        #pragma unroll 1
        for (int task = tid; task < NTASK; task += NTHR) {
            int rg = task / IN_W;
            int c  = task - rg * IN_W;
            vtask<true>(img1, img2, base, bx0, by0, c, rg * RV,
                        wp, vbA, vb4);
        }
    }
    __syncthreads();

    // ---- Horizontal pass + SSIM ----
    const int r  = tid & (TH - 1);       // lanes -> consecutive rows
    const int x0 = (tid >> 5) * RH;      // 8 x-groups of RH outputs

    u64 b01[RH], b23[RH];
    float b4[RH];
    #pragma unroll
    for (int j = 0; j < RH; ++j) { b01[j] = 0ull; b23[j] = 0ull; b4[j] = 0.f; }

    #pragma unroll
    for (int i = 0; i < RH + KSZ - 1; ++i) {          // 18 x positions
        int o = (x0 + i) * VBP2 + r;
        ulonglong2 v = vbA[o];                        // LDS.128
        u64 v01 = v.x;
        u64 v23 = v.y;
        float v4 = vb4[o];
        #pragma unroll
        for (int j = 0; j < RH; ++j) {
            int k = i - j;
            if (k >= 0 && k < KSZ) {
                b01[j] = fma2(wsym(wp, k), v01, b01[j]);
                b23[j] = fma2(wsym(wp, k), v23, b23[j]);
                b4[j] += GW[k] * v4;                  // FFMA-imm
            }
        }
    }

    const float C1 = 1e-4f, C2 = 9e-4f;
    float ssum = 0.f;
    #pragma unroll
    for (int j = 0; j < RH; ++j) {
        float mx, my, mxx, myy;
        unpack2(b01[j], mx, my);
        unpack2(b23[j], mxx, myy);
        float mxy = b4[j];
        float mx2 = mx * mx, my2 = my * my, mxmy = mx * my;
        float sxx = mxx - mx2;
        float syy = myy - my2;
        float sxy = mxy - mxmy;
        float num = (2.f * mxmy + C1) * (2.f * sxy + C2);
        float den = (mx2 + my2 + C1) * (sxx + syy + C2);
        ssum += __fdividef(num, den);
    }

    // ---- Block reduce -> one double atomic per block ----
    #pragma unroll
    for (int o = 16; o > 0; o >>= 1)
        ssum += __shfl_down_sync(0xffffffffu, ssum, o);
    int lane = tid & 31, wid = tid >> 5;
    if (lane == 0) warpsum[wid] = ssum;
    __syncthreads();
    if (wid == 0 && lane == 0) {
        float v = 0.f;
        #pragma unroll
        for (int w = 0; w < NTHR / 32; ++w) v += warpsum[w];
        atomicAdd(&g_acc, (double)v);

        // Last-block-done finalize: write mean, reset accumulator for the
        // next graph replay. atomicInc wraps the counter back to 0.
        __threadfence();
        unsigned int prev = atomicInc(&g_done, nblocks - 1);
        if (prev == nblocks - 1) {
            __threadfence();
            out[0] = (float)(g_acc * inv_n);
            g_acc = 0.0;
        }
    }
}

extern "C" void kernel_launch(void* const* d_in, const int* in_sizes, int n_in,
                              void* d_out, int out_size) {
    const float* img1 = (const float*)d_in[0];
    const float* img2 = (const float*)d_in[1];
    float* out = (float*)d_out;

    const int B = in_sizes[0] / (IMG_W * IMG_H);

    const int smem_bytes = IN_W * VBP2 * (16 + 4);   // 48840 B (unchanged)
    cudaFuncSetAttribute(ssim_main, cudaFuncAttributeMaxDynamicSharedMemorySize,
                         smem_bytes);

    dim3 blk(NTHR);
    dim3 grd(IMG_W / TW, IMG_H / TH, B);
    unsigned int nblocks = grd.x * grd.y * grd.z;
    double inv_n = 1.0 / ((double)B * IMG_W * IMG_H);

    ssim_main<<<grd, blk, smem_bytes>>>(img1, img2, out, nblocks, inv_n);
}